// round 8
// baseline (speedup 1.0000x reference)
#include <cuda_runtime.h>
#include <cuda_fp16.h>
#include <math.h>

#define NMAX 100000
#define EMAX 1000000
#define F    64
#define FO   16

// ---------------- scratch (no allocations allowed) ----------------
__device__ int    g_hist[NMAX];
__device__ int    g_rank[EMAX];
__device__ int    g_rowptr[NMAX + 1];
__device__ int    g_col [EMAX];
__device__ float  g_w   [EMAX];
__device__ float  g_dinv[NMAX];
__device__ __half g_bufH1[(size_t)NMAX * F];
__device__ __half g_bufH2[(size_t)NMAX * F];
__device__ float  g_buf16[(size_t)NMAX * FO];
__device__ int    g_part[1024];

// ---------------- CSR build ----------------
// histogram + per-edge rank in one atomic pass
__global__ void k_hist_rank(const int* __restrict__ ei, int E) {
    int e = blockIdx.x * blockDim.x + threadIdx.x;
    if (e < E) g_rank[e] = atomicAdd(&g_hist[ei[e]], 1);
}

// block-local exclusive scan (1024 threads) + dinv
__global__ void k_scan_block(int n) {
    __shared__ int sh[1024];
    int gid = blockIdx.x * 1024 + threadIdx.x;
    int v = (gid < n) ? g_hist[gid] : 0;
    if (gid < n) g_dinv[gid] = rsqrtf((float)v + 1.0f);   // +1 self loop
    sh[threadIdx.x] = v;
    __syncthreads();
    #pragma unroll
    for (int off = 1; off < 1024; off <<= 1) {
        int t = (threadIdx.x >= off) ? sh[threadIdx.x - off] : 0;
        __syncthreads();
        sh[threadIdx.x] += t;
        __syncthreads();
    }
    if (gid < n) g_rowptr[gid] = sh[threadIdx.x] - v;     // exclusive
    if (threadIdx.x == 1023) g_part[blockIdx.x] = sh[1023];
}

// add sum of partials below this block (fused part-scan), set rowptr[n]
__global__ void k_scan_add(int n, int Etot) {
    __shared__ int sred[1024];
    int v = (threadIdx.x < blockIdx.x) ? g_part[threadIdx.x] : 0;
    sred[threadIdx.x] = v;
    __syncthreads();
    #pragma unroll
    for (int off = 512; off >= 1; off >>= 1) {
        if (threadIdx.x < off) sred[threadIdx.x] += sred[threadIdx.x + off];
        __syncthreads();
    }
    int base = sred[0];
    int gid = blockIdx.x * 1024 + threadIdx.x;
    if (gid < n) g_rowptr[gid] += base;
    if (gid == 0) g_rowptr[n] = Etot;
}

// atomic-free fill using precomputed ranks
__global__ void k_fill(const int* __restrict__ ei, int E) {
    int e = blockIdx.x * blockDim.x + threadIdx.x;
    if (e >= E) return;
    int r = ei[e];
    int c = ei[E + e];
    int pos = g_rowptr[r] + g_rank[e];
    g_col[pos] = c;
    g_w[pos]   = g_dinv[r] * g_dinv[c];
}

// ---------------- x (fp32) -> fp16 ----------------
__global__ void k_cvt(const float* __restrict__ x, __half* __restrict__ dst, int total4) {
    int i = blockIdx.x * blockDim.x + threadIdx.x;   // one float4 -> half4
    if (i >= total4) return;
    float4 v = ((const float4*)x)[i];
    __half2 lo = __floats2half2_rn(v.x, v.y);
    __half2 hi = __floats2half2_rn(v.z, v.w);
    uint2 u;
    u.x = *(unsigned*)&lo; u.y = *(unsigned*)&hi;
    ((uint2*)dst)[i] = u;
}

// ---------------- fp16 SpMM core: 8 lanes/node, 8 features per lane ----------
__device__ __forceinline__ void h8_acc(uint4 u, float w, float* acc) {
    __half2* h = (__half2*)&u;
    float2 f0 = __half22float2(h[0]);
    float2 f1 = __half22float2(h[1]);
    float2 f2 = __half22float2(h[2]);
    float2 f3 = __half22float2(h[3]);
    acc[0] += w * f0.x; acc[1] += w * f0.y;
    acc[2] += w * f1.x; acc[3] += w * f1.y;
    acc[4] += w * f2.x; acc[5] += w * f2.y;
    acc[6] += w * f3.x; acc[7] += w * f3.y;
}

__device__ __forceinline__ void spmm_row_h(const __half* __restrict__ src, int node,
                                           int l8, float* acc) {
    float d  = g_dinv[node];
    float sw = d * d;
    #pragma unroll
    for (int i = 0; i < 8; i++) acc[i] = 0.f;
    h8_acc(((const uint4*)(src + (size_t)node * F))[l8], sw, acc);
    int s = g_rowptr[node], e = g_rowptr[node + 1];
    int p = s;
    // main: unclamped batches of 8 (8 independent LDG.128 in flight)
    for (; p + 8 <= e; p += 8) {
        int jj[8]; float ww[8];
        #pragma unroll
        for (int q = 0; q < 8; q++) { jj[q] = g_col[p + q]; ww[q] = g_w[p + q]; }
        uint4 vv[8];
        #pragma unroll
        for (int q = 0; q < 8; q++)
            vv[q] = ((const uint4*)(src + (size_t)jj[q] * F))[l8];
        #pragma unroll
        for (int q = 0; q < 8; q++)
            h8_acc(vv[q], ww[q], acc);
    }
    // tail: clamped predicated batches of 4 — no serial dependent chain
    for (; p < e; p += 4) {
        int jj[4]; float ww[4];
        #pragma unroll
        for (int q = 0; q < 4; q++) {
            int idx = p + q;
            bool ok = idx < e;
            int ci  = ok ? idx : s;      // s < e guaranteed (p < e)
            jj[q] = g_col[ci];
            ww[q] = ok ? g_w[ci] : 0.f;
        }
        uint4 vv[4];
        #pragma unroll
        for (int q = 0; q < 4; q++)
            vv[q] = ((const uint4*)(src + (size_t)jj[q] * F))[l8];
        #pragma unroll
        for (int q = 0; q < 4; q++)
            h8_acc(vv[q], ww[q], acc);
    }
}

__device__ __forceinline__ uint4 f8_to_h8(const float* acc) {
    __half2 h0 = __floats2half2_rn(acc[0], acc[1]);
    __half2 h1 = __floats2half2_rn(acc[2], acc[3]);
    __half2 h2 = __floats2half2_rn(acc[4], acc[5]);
    __half2 h3 = __floats2half2_rn(acc[6], acc[7]);
    uint4 u;
    u.x = *(unsigned*)&h0; u.y = *(unsigned*)&h1;
    u.z = *(unsigned*)&h2; u.w = *(unsigned*)&h3;
    return u;
}

__global__ void k_spmm_h(const __half* __restrict__ src, __half* __restrict__ dst, int n) {
    int tid  = blockIdx.x * blockDim.x + threadIdx.x;
    int node = tid >> 3;
    int l8   = tid & 7;
    if (node >= n) return;
    float acc[8];
    spmm_row_h(src, node, l8, acc);
    ((uint4*)(dst + (size_t)node * F))[l8] = f8_to_h8(acc);
}

// ---------------- hop4 fused: fp16 SpMM + W1 + SELU + W2 -> N x 16 -----------
#define PAD 4
__global__ void k_hop4_fused(const __half* __restrict__ src, float* __restrict__ dst16,
                             const float* __restrict__ W1, const float* __restrict__ b1,
                             const float* __restrict__ W2, const float* __restrict__ b2, int n) {
    __shared__ float W1s[F * F];
    __shared__ float W2s[F * FO];
    __shared__ float b2s[FO];
    __shared__ float y_s[32][F + PAD];
    __shared__ float h_s[32][F + PAD];
    for (int t = threadIdx.x; t < F * F; t += blockDim.x) W1s[t] = W1[t];
    for (int t = threadIdx.x; t < F * FO; t += blockDim.x) W2s[t] = W2[t];
    if (threadIdx.x < FO) b2s[threadIdx.x] = b2[threadIdx.x];
    __syncthreads();

    int nodeL = threadIdx.x >> 3;
    int l8    = threadIdx.x & 7;
    int node  = blockIdx.x * 32 + nodeL;

    float acc[8];
    #pragma unroll
    for (int i = 0; i < 8; i++) acc[i] = 0.f;
    if (node < n) spmm_row_h(src, node, l8, acc);
    ((float4*)&y_s[nodeL][8 * l8])[0]     = make_float4(acc[0], acc[1], acc[2], acc[3]);
    ((float4*)&y_s[nodeL][8 * l8 + 4])[0] = make_float4(acc[4], acc[5], acc[6], acc[7]);
    __syncwarp();

    // GEMM1 + SELU: lane l8 computes features l8 + 8*m, m=0..7
    float h[8];
    #pragma unroll
    for (int m = 0; m < 8; m++) h[m] = b1[l8 + 8 * m];
    #pragma unroll 8
    for (int k = 0; k < F; k++) {
        float yk = y_s[nodeL][k];
        #pragma unroll
        for (int m = 0; m < 8; m++)
            h[m] += yk * W1s[k * F + l8 + 8 * m];
    }
    const float al = 1.6732632423543772f, sc = 1.0507009873554805f;
    #pragma unroll
    for (int m = 0; m < 8; m++) {
        h[m] = (h[m] > 0.f) ? sc * h[m] : sc * al * expm1f(h[m]);
        h_s[nodeL][l8 + 8 * m] = h[m];
    }
    __syncwarp();

    // GEMM2: lane l8 computes output features l8 and l8+8
    float z0 = b2s[l8], z1 = b2s[l8 + 8];
    #pragma unroll 8
    for (int k = 0; k < F; k++) {
        float hk = h_s[nodeL][k];
        z0 += hk * W2s[k * FO + l8];
        z1 += hk * W2s[k * FO + l8 + 8];
    }
    if (node < n) {
        dst16[(size_t)node * FO + l8]     = z0;
        dst16[(size_t)node * FO + l8 + 8] = z1;
    }
}

// ---------------- final 16-wide hop + log_softmax: 4 lanes/node, float4 -------
__global__ void k_hop16(const float* __restrict__ src16, float* __restrict__ out, int n) {
    int tid  = blockIdx.x * blockDim.x + threadIdx.x;
    int node = tid >> 2;
    int l4   = tid & 3;
    if (node >= n) return;
    float d = g_dinv[node];
    float sw = d * d;
    float4 a = ((const float4*)(src16 + (size_t)node * FO))[l4];
    float4 acc = make_float4(sw * a.x, sw * a.y, sw * a.z, sw * a.w);
    int s = g_rowptr[node], e = g_rowptr[node + 1];
    int p = s;
    for (; p + 4 <= e; p += 4) {
        int   j0 = g_col[p],   j1 = g_col[p + 1], j2 = g_col[p + 2], j3 = g_col[p + 3];
        float w0 = g_w[p],     w1 = g_w[p + 1],   w2 = g_w[p + 2],   w3 = g_w[p + 3];
        float4 v0 = ((const float4*)(src16 + (size_t)j0 * FO))[l4];
        float4 v1 = ((const float4*)(src16 + (size_t)j1 * FO))[l4];
        float4 v2 = ((const float4*)(src16 + (size_t)j2 * FO))[l4];
        float4 v3 = ((const float4*)(src16 + (size_t)j3 * FO))[l4];
        acc.x += w0 * v0.x + w1 * v1.x + w2 * v2.x + w3 * v3.x;
        acc.y += w0 * v0.y + w1 * v1.y + w2 * v2.y + w3 * v3.y;
        acc.z += w0 * v0.z + w1 * v1.z + w2 * v2.z + w3 * v3.z;
        acc.w += w0 * v0.w + w1 * v1.w + w2 * v2.w + w3 * v3.w;
    }
    // clamped predicated tail batch of 4
    if (p < e) {
        #pragma unroll
        for (int q = 0; q < 4; q++) {
            int idx = p + q;
            bool ok = idx < e;
            int ci  = ok ? idx : s;
            int j = g_col[ci];
            float w = ok ? g_w[ci] : 0.f;
            float4 v = ((const float4*)(src16 + (size_t)j * FO))[l4];
            acc.x += w * v.x; acc.y += w * v.y; acc.z += w * v.z; acc.w += w * v.w;
        }
    }

    float m = fmaxf(fmaxf(acc.x, acc.y), fmaxf(acc.z, acc.w));
    m = fmaxf(m, __shfl_xor_sync(0xffffffffu, m, 1, 4));
    m = fmaxf(m, __shfl_xor_sync(0xffffffffu, m, 2, 4));
    float ssum = expf(acc.x - m) + expf(acc.y - m) + expf(acc.z - m) + expf(acc.w - m);
    ssum += __shfl_xor_sync(0xffffffffu, ssum, 1, 4);
    ssum += __shfl_xor_sync(0xffffffffu, ssum, 2, 4);
    float lse = m + logf(ssum);
    float4 r = make_float4(acc.x - lse, acc.y - lse, acc.z - lse, acc.w - lse);
    ((float4*)(out + (size_t)node * FO))[l4] = r;
}

// ---------------- launch ----------------
extern "C" void kernel_launch(void* const* d_in, const int* in_sizes, int n_in,
                              void* d_out, int out_size) {
    const float* x  = (const float*)d_in[0];
    const float* W1 = (const float*)d_in[1];
    const float* b1 = (const float*)d_in[2];
    const float* W2 = (const float*)d_in[3];
    const float* b2 = (const float*)d_in[4];
    const int*   ei = (const int*)  d_in[5];
    int N = in_sizes[0] / F;
    int E = in_sizes[5] / 2;
    float* out = (float*)d_out;

    __half *H1, *H2;
    float  *buf16;
    int *histp;
    cudaGetSymbolAddress((void**)&H1, g_bufH1);
    cudaGetSymbolAddress((void**)&H2, g_bufH2);
    cudaGetSymbolAddress((void**)&buf16, g_buf16);
    cudaGetSymbolAddress((void**)&histp, g_hist);

    int tb = 256;
    int nbE    = (E + tb - 1) / tb;
    int nb1024 = (N + 1023) / 1024;
    int nbC    = (N * F / 4 + tb - 1) / tb;    // convert: float4 per thread
    int nb8    = (N * 8 + tb - 1) / tb;        // 8 lanes/node
    int nbF    = (N + 31) / 32;                // hop4 fused: 32 nodes/block
    int nbQ    = (N * 4 + tb - 1) / tb;        // 4 lanes/node

    // CSR build (rank-based, atomic-free fill)
    cudaMemsetAsync(histp, 0, (size_t)N * sizeof(int));
    k_hist_rank <<<nbE, tb>>>(ei, E);
    k_scan_block<<<nb1024, 1024>>>(N);
    k_scan_add  <<<nb1024, 1024>>>(N, E);
    k_fill      <<<nbE, tb>>>(ei, E);

    // convert x to fp16, then 3 fp16 hops, then hop4 fused with GEMM1+SELU+GEMM2
    k_cvt   <<<nbC, tb>>>(x, H1, N * F / 4);
    k_spmm_h<<<nb8, tb>>>(H1, H2, N);
    k_spmm_h<<<nb8, tb>>>(H2, H1, N);
    k_spmm_h<<<nb8, tb>>>(H1, H2, N);
    k_hop4_fused<<<nbF, tb>>>(H2, buf16, W1, b1, W2, b2, N);

    // conv2: 16-wide hop + log_softmax
    k_hop16<<<nbQ, tb>>>(buf16, out, N);
}

// round 9
// speedup vs baseline: 1.0434x; 1.0434x over previous
#include <cuda_runtime.h>
#include <cuda_fp16.h>
#include <math.h>

#define NMAX 100000
#define EMAX 1000000
#define F    64
#define FO   16

// ---------------- scratch (no allocations allowed) ----------------
__device__ int    g_hist[NMAX];
__device__ int    g_rank[EMAX];
__device__ int    g_rowptr[NMAX + 1];
__device__ int2   g_colw[EMAX];          // packed (col, w-bits)
__device__ float  g_dinv[NMAX];
__device__ __half g_bufH1[(size_t)NMAX * F];
__device__ __half g_bufH2[(size_t)NMAX * F];
__device__ float  g_buf16[(size_t)NMAX * FO];
__device__ int    g_part[1024];

// ---------------- CSR build ----------------
// histogram + per-edge rank in one atomic pass
__global__ void k_hist_rank(const int* __restrict__ ei, int E) {
    int e = blockIdx.x * blockDim.x + threadIdx.x;
    if (e < E) g_rank[e] = atomicAdd(&g_hist[ei[e]], 1);
}

// block-local exclusive scan (1024 threads) + dinv
__global__ void k_scan_block(int n) {
    __shared__ int sh[1024];
    int gid = blockIdx.x * 1024 + threadIdx.x;
    int v = (gid < n) ? g_hist[gid] : 0;
    if (gid < n) g_dinv[gid] = rsqrtf((float)v + 1.0f);   // +1 self loop
    sh[threadIdx.x] = v;
    __syncthreads();
    #pragma unroll
    for (int off = 1; off < 1024; off <<= 1) {
        int t = (threadIdx.x >= off) ? sh[threadIdx.x - off] : 0;
        __syncthreads();
        sh[threadIdx.x] += t;
        __syncthreads();
    }
    if (gid < n) g_rowptr[gid] = sh[threadIdx.x] - v;     // exclusive
    if (threadIdx.x == 1023) g_part[blockIdx.x] = sh[1023];
}

// add sum of partials below this block (fused part-scan), set rowptr[n]
__global__ void k_scan_add(int n, int Etot) {
    __shared__ int sred[1024];
    int v = (threadIdx.x < blockIdx.x) ? g_part[threadIdx.x] : 0;
    sred[threadIdx.x] = v;
    __syncthreads();
    #pragma unroll
    for (int off = 512; off >= 1; off >>= 1) {
        if (threadIdx.x < off) sred[threadIdx.x] += sred[threadIdx.x + off];
        __syncthreads();
    }
    int base = sred[0];
    int gid = blockIdx.x * 1024 + threadIdx.x;
    if (gid < n) g_rowptr[gid] += base;
    if (gid == 0) g_rowptr[n] = Etot;
}

// atomic-free fill using precomputed ranks; one packed 8B store per edge
__global__ void k_fill(const int* __restrict__ ei, int E) {
    int e = blockIdx.x * blockDim.x + threadIdx.x;
    if (e >= E) return;
    int r = ei[e];
    int c = ei[E + e];
    int pos = g_rowptr[r] + g_rank[e];
    float w = g_dinv[r] * g_dinv[c];
    g_colw[pos] = make_int2(c, __float_as_int(w));
}

// ---------------- x (fp32) -> fp16 ----------------
__global__ void k_cvt(const float* __restrict__ x, __half* __restrict__ dst, int total4) {
    int i = blockIdx.x * blockDim.x + threadIdx.x;   // one float4 -> half4
    if (i >= total4) return;
    float4 v = ((const float4*)x)[i];
    __half2 lo = __floats2half2_rn(v.x, v.y);
    __half2 hi = __floats2half2_rn(v.z, v.w);
    uint2 u;
    u.x = *(unsigned*)&lo; u.y = *(unsigned*)&hi;
    ((uint2*)dst)[i] = u;
}

// ---------------- fp16 SpMM core: 8 lanes/node, 8 features per lane ----------
__device__ __forceinline__ void h8_acc(uint4 u, float w, float* acc) {
    __half2* h = (__half2*)&u;
    float2 f0 = __half22float2(h[0]);
    float2 f1 = __half22float2(h[1]);
    float2 f2 = __half22float2(h[2]);
    float2 f3 = __half22float2(h[3]);
    acc[0] += w * f0.x; acc[1] += w * f0.y;
    acc[2] += w * f1.x; acc[3] += w * f1.y;
    acc[4] += w * f2.x; acc[5] += w * f2.y;
    acc[6] += w * f3.x; acc[7] += w * f3.y;
}

__device__ __forceinline__ void spmm_row_h(const __half* __restrict__ src, int node,
                                           int l8, float* acc) {
    float d  = g_dinv[node];
    float sw = d * d;
    #pragma unroll
    for (int i = 0; i < 8; i++) acc[i] = 0.f;
    h8_acc(((const uint4*)(src + (size_t)node * F))[l8], sw, acc);
    int s = g_rowptr[node], e = g_rowptr[node + 1];
    int p = s;
    // main: batches of 8 (8 independent LDG.128 in flight)
    for (; p + 8 <= e; p += 8) {
        int jj[8]; float ww[8];
        #pragma unroll
        for (int q = 0; q < 8; q++) {
            int2 cw = g_colw[p + q];
            jj[q] = cw.x; ww[q] = __int_as_float(cw.y);
        }
        uint4 vv[8];
        #pragma unroll
        for (int q = 0; q < 8; q++)
            vv[q] = ((const uint4*)(src + (size_t)jj[q] * F))[l8];
        #pragma unroll
        for (int q = 0; q < 8; q++)
            h8_acc(vv[q], ww[q], acc);
    }
    if (p + 4 <= e) {
        int jj[4]; float ww[4];
        #pragma unroll
        for (int q = 0; q < 4; q++) {
            int2 cw = g_colw[p + q];
            jj[q] = cw.x; ww[q] = __int_as_float(cw.y);
        }
        uint4 vv[4];
        #pragma unroll
        for (int q = 0; q < 4; q++)
            vv[q] = ((const uint4*)(src + (size_t)jj[q] * F))[l8];
        #pragma unroll
        for (int q = 0; q < 4; q++)
            h8_acc(vv[q], ww[q], acc);
        p += 4;
    }
    for (; p < e; p++) {
        int2 cw = g_colw[p];
        uint4 v = ((const uint4*)(src + (size_t)cw.x * F))[l8];
        h8_acc(v, __int_as_float(cw.y), acc);
    }
}

__device__ __forceinline__ uint4 f8_to_h8(const float* acc) {
    __half2 h0 = __floats2half2_rn(acc[0], acc[1]);
    __half2 h1 = __floats2half2_rn(acc[2], acc[3]);
    __half2 h2 = __floats2half2_rn(acc[4], acc[5]);
    __half2 h3 = __floats2half2_rn(acc[6], acc[7]);
    uint4 u;
    u.x = *(unsigned*)&h0; u.y = *(unsigned*)&h1;
    u.z = *(unsigned*)&h2; u.w = *(unsigned*)&h3;
    return u;
}

__global__ void k_spmm_h(const __half* __restrict__ src, __half* __restrict__ dst, int n) {
    int tid  = blockIdx.x * blockDim.x + threadIdx.x;
    int node = tid >> 3;
    int l8   = tid & 7;
    if (node >= n) return;
    float acc[8];
    spmm_row_h(src, node, l8, acc);
    ((uint4*)(dst + (size_t)node * F))[l8] = f8_to_h8(acc);
}

// ---------------- hop4 fused: fp16 SpMM + W1 + SELU + W2 -> N x 16 -----------
#define PAD 4
__global__ void k_hop4_fused(const __half* __restrict__ src, float* __restrict__ dst16,
                             const float* __restrict__ W1, const float* __restrict__ b1,
                             const float* __restrict__ W2, const float* __restrict__ b2, int n) {
    __shared__ float W1s[F * F];
    __shared__ float W2s[F * FO];
    __shared__ float b2s[FO];
    __shared__ float y_s[32][F + PAD];
    __shared__ float h_s[32][F + PAD];
    for (int t = threadIdx.x; t < F * F; t += blockDim.x) W1s[t] = W1[t];
    for (int t = threadIdx.x; t < F * FO; t += blockDim.x) W2s[t] = W2[t];
    if (threadIdx.x < FO) b2s[threadIdx.x] = b2[threadIdx.x];
    __syncthreads();

    int nodeL = threadIdx.x >> 3;
    int l8    = threadIdx.x & 7;
    int node  = blockIdx.x * 32 + nodeL;

    float acc[8];
    #pragma unroll
    for (int i = 0; i < 8; i++) acc[i] = 0.f;
    if (node < n) spmm_row_h(src, node, l8, acc);
    ((float4*)&y_s[nodeL][8 * l8])[0]     = make_float4(acc[0], acc[1], acc[2], acc[3]);
    ((float4*)&y_s[nodeL][8 * l8 + 4])[0] = make_float4(acc[4], acc[5], acc[6], acc[7]);
    __syncwarp();

    // GEMM1 + SELU: lane l8 computes features l8 + 8*m, m=0..7
    float h[8];
    #pragma unroll
    for (int m = 0; m < 8; m++) h[m] = b1[l8 + 8 * m];
    #pragma unroll 8
    for (int k = 0; k < F; k++) {
        float yk = y_s[nodeL][k];
        #pragma unroll
        for (int m = 0; m < 8; m++)
            h[m] += yk * W1s[k * F + l8 + 8 * m];
    }
    const float al = 1.6732632423543772f, sc = 1.0507009873554805f;
    #pragma unroll
    for (int m = 0; m < 8; m++) {
        h[m] = (h[m] > 0.f) ? sc * h[m] : sc * al * expm1f(h[m]);
        h_s[nodeL][l8 + 8 * m] = h[m];
    }
    __syncwarp();

    // GEMM2: lane l8 computes output features l8 and l8+8
    float z0 = b2s[l8], z1 = b2s[l8 + 8];
    #pragma unroll 8
    for (int k = 0; k < F; k++) {
        float hk = h_s[nodeL][k];
        z0 += hk * W2s[k * FO + l8];
        z1 += hk * W2s[k * FO + l8 + 8];
    }
    if (node < n) {
        dst16[(size_t)node * FO + l8]     = z0;
        dst16[(size_t)node * FO + l8 + 8] = z1;
    }
}

// ---------------- final 16-wide hop + log_softmax: 4 lanes/node, float4 -------
__global__ void k_hop16(const float* __restrict__ src16, float* __restrict__ out, int n) {
    int tid  = blockIdx.x * blockDim.x + threadIdx.x;
    int node = tid >> 2;
    int l4   = tid & 3;
    if (node >= n) return;
    float d = g_dinv[node];
    float sw = d * d;
    float4 a = ((const float4*)(src16 + (size_t)node * FO))[l4];
    float4 acc = make_float4(sw * a.x, sw * a.y, sw * a.z, sw * a.w);
    int s = g_rowptr[node], e = g_rowptr[node + 1];
    int p = s;
    for (; p + 4 <= e; p += 4) {
        int jj[4]; float ww[4];
        #pragma unroll
        for (int q = 0; q < 4; q++) {
            int2 cw = g_colw[p + q];
            jj[q] = cw.x; ww[q] = __int_as_float(cw.y);
        }
        float4 v0 = ((const float4*)(src16 + (size_t)jj[0] * FO))[l4];
        float4 v1 = ((const float4*)(src16 + (size_t)jj[1] * FO))[l4];
        float4 v2 = ((const float4*)(src16 + (size_t)jj[2] * FO))[l4];
        float4 v3 = ((const float4*)(src16 + (size_t)jj[3] * FO))[l4];
        acc.x += ww[0] * v0.x + ww[1] * v1.x + ww[2] * v2.x + ww[3] * v3.x;
        acc.y += ww[0] * v0.y + ww[1] * v1.y + ww[2] * v2.y + ww[3] * v3.y;
        acc.z += ww[0] * v0.z + ww[1] * v1.z + ww[2] * v2.z + ww[3] * v3.z;
        acc.w += ww[0] * v0.w + ww[1] * v1.w + ww[2] * v2.w + ww[3] * v3.w;
    }
    for (; p < e; p++) {
        int2 cw = g_colw[p];
        float w = __int_as_float(cw.y);
        float4 v = ((const float4*)(src16 + (size_t)cw.x * FO))[l4];
        acc.x += w * v.x; acc.y += w * v.y; acc.z += w * v.z; acc.w += w * v.w;
    }

    float m = fmaxf(fmaxf(acc.x, acc.y), fmaxf(acc.z, acc.w));
    m = fmaxf(m, __shfl_xor_sync(0xffffffffu, m, 1, 4));
    m = fmaxf(m, __shfl_xor_sync(0xffffffffu, m, 2, 4));
    float ssum = expf(acc.x - m) + expf(acc.y - m) + expf(acc.z - m) + expf(acc.w - m);
    ssum += __shfl_xor_sync(0xffffffffu, ssum, 1, 4);
    ssum += __shfl_xor_sync(0xffffffffu, ssum, 2, 4);
    float lse = m + logf(ssum);
    float4 r = make_float4(acc.x - lse, acc.y - lse, acc.z - lse, acc.w - lse);
    ((float4*)(out + (size_t)node * FO))[l4] = r;
}

// ---------------- launch ----------------
extern "C" void kernel_launch(void* const* d_in, const int* in_sizes, int n_in,
                              void* d_out, int out_size) {
    const float* x  = (const float*)d_in[0];
    const float* W1 = (const float*)d_in[1];
    const float* b1 = (const float*)d_in[2];
    const float* W2 = (const float*)d_in[3];
    const float* b2 = (const float*)d_in[4];
    const int*   ei = (const int*)  d_in[5];
    int N = in_sizes[0] / F;
    int E = in_sizes[5] / 2;
    float* out = (float*)d_out;

    __half *H1, *H2;
    float  *buf16;
    int *histp;
    cudaGetSymbolAddress((void**)&H1, g_bufH1);
    cudaGetSymbolAddress((void**)&H2, g_bufH2);
    cudaGetSymbolAddress((void**)&buf16, g_buf16);
    cudaGetSymbolAddress((void**)&histp, g_hist);

    int tb = 256;
    int nbE    = (E + tb - 1) / tb;
    int nb1024 = (N + 1023) / 1024;
    int nbC    = (N * F / 4 + tb - 1) / tb;    // convert: float4 per thread
    int nb8    = (N * 8 + tb - 1) / tb;        // 8 lanes/node
    int nbF    = (N + 31) / 32;                // hop4 fused: 32 nodes/block
    int nbQ    = (N * 4 + tb - 1) / tb;        // 4 lanes/node

    // CSR build (rank-based, atomic-free fill; packed colw)
    cudaMemsetAsync(histp, 0, (size_t)N * sizeof(int));
    k_hist_rank <<<nbE, tb>>>(ei, E);
    k_cvt       <<<nbC, tb>>>(x, H1, N * F / 4);   // independent of CSR; fills pipeline
    k_scan_block<<<nb1024, 1024>>>(N);
    k_scan_add  <<<nb1024, 1024>>>(N, E);
    k_fill      <<<nbE, tb>>>(ei, E);

    // 3 fp16 hops, then hop4 fused with GEMM1+SELU+GEMM2
    k_spmm_h<<<nb8, tb>>>(H1, H2, N);
    k_spmm_h<<<nb8, tb>>>(H2, H1, N);
    k_spmm_h<<<nb8, tb>>>(H1, H2, N);
    k_hop4_fused<<<nbF, tb>>>(H2, buf16, W1, b1, W2, b2, N);

    // conv2: 16-wide hop + log_softmax
    k_hop16<<<nbQ, tb>>>(buf16, out, N);
}